// round 16
// baseline (speedup 1.0000x reference)
#include <cuda_runtime.h>
#include <cuda_fp16.h>
#include <cstdint>

#define GRID_H 1024
#define GRID_W 1024
#define DIM_FEAT 32
#define HW (GRID_H * GRID_W)
#define HALF_C 16
#define HALF_ELEMS ((size_t)HW * HALF_C)

// 64 MB table split into two contiguous 32MB channel-halves:
// half h holds channels [16h, 16h+16) of every pixel, [HW, 16] layout.
__device__ __half g_params_t[2 * HALF_ELEMS];

// ---------------------------------------------------------------------------
// Transpose [C, H*W] fp32 -> two half-tables [HW, 16] fp16.
// Tile: 32 channels x 64 pixels; float4 reads, 16B writes.
// ---------------------------------------------------------------------------
__global__ void __launch_bounds__(256)
transpose_kernel(const float* __restrict__ p, __half* __restrict__ pt) {
    __shared__ float tile[32][65];
    const int pix0 = blockIdx.x * 64;
    const int t = threadIdx.x;      // 0..255

    // Read phase: thread covers float4 xq of channels c and c+16.
    {
        const int c = t >> 4;         // 0..15
        const int xq = t & 15;        // float4 index (64 pixels)
        const float4 a = __ldcs((const float4*)(p + (size_t)c * HW + pix0) + xq);
        const float4 b = __ldcs((const float4*)(p + (size_t)(c + 16) * HW + pix0) + xq);
        tile[c][4 * xq + 0] = a.x;
        tile[c][4 * xq + 1] = a.y;
        tile[c][4 * xq + 2] = a.z;
        tile[c][4 * xq + 3] = a.w;
        tile[c + 16][4 * xq + 0] = b.x;
        tile[c + 16][4 * xq + 1] = b.y;
        tile[c + 16][4 * xq + 2] = b.z;
        tile[c + 16][4 * xq + 3] = b.w;
    }
    __syncthreads();

    // Write phase: thread covers 8 channels (cg) of one pixel -> 16B store
    // into half (cg>>1) at slot (cg&1)*8.
    {
        const int pix = t >> 2;       // 0..63
        const int cg = t & 3;         // channel group
        const int c0 = 8 * cg;
        const int h = cg >> 1;
        uint4 v;
        unsigned* vp = (unsigned*)&v;
#pragma unroll
        for (int j = 0; j < 4; j++) {
            const __half2 hh = __floats2half2_rn(tile[c0 + 2 * j][pix],
                                                 tile[c0 + 2 * j + 1][pix]);
            vp[j] = *(const unsigned*)&hh;
        }
        *(uint4*)(pt + (size_t)h * HALF_ELEMS +
                  (size_t)(pix0 + pix) * HALF_C + (cg & 1) * 8) = v;
    }
}

// 256-bit streaming store.
__device__ __forceinline__ void stcs_v8(float* p, const float a[8]) {
    asm volatile(
        "st.global.cs.v8.b32 [%0], {%1,%2,%3,%4,%5,%6,%7,%8};"
        :: "l"(p),
           "f"(a[0]), "f"(a[1]), "f"(a[2]), "f"(a[3]),
           "f"(a[4]), "f"(a[5]), "f"(a[6]), "f"(a[7])
        : "memory");
}

// ---------------------------------------------------------------------------
// Bilinear sample over ONE channel-half (32MB live table -> L2-resident).
// 2 lanes per point, lane = 8 channels: 4 x 16B uint4 gathers
// (32B per corner across lanes); one 32B v8 streaming store per lane.
// ---------------------------------------------------------------------------
__global__ void __launch_bounds__(256, 8)
sample_kernel(const float2* __restrict__ coord,
              const __half* __restrict__ tbl,   // half-table base
              float* __restrict__ out,          // out + pass*16 already applied
              int n) {
    const int t = blockIdx.x * blockDim.x + threadIdx.x;
    const int pidx = t >> 1;     // point index
    const int lane = t & 1;      // channel octet within the half
    if (pidx >= n) return;

    const float2 xy = __ldcs(&coord[pidx]);

    // align_corners=True mapping
    const float ix = (xy.x + 1.0f) * 0.5f * (float)(GRID_W - 1);
    const float iy = (xy.y + 1.0f) * 0.5f * (float)(GRID_H - 1);

    const float ix0f = floorf(ix);
    const float iy0f = floorf(iy);
    const float fx = ix - ix0f;
    const float fy = iy - iy0f;

    const float w_nw = (1.0f - fx) * (1.0f - fy);
    const float w_ne = fx * (1.0f - fy);
    const float w_sw = (1.0f - fx) * fy;
    const float w_se = fx * fy;

    int ix0 = min(max((int)ix0f, 0), GRID_W - 1);
    int iy0 = min(max((int)iy0f, 0), GRID_H - 1);
    const int ix1 = min(ix0 + 1, GRID_W - 1);
    const int iy1 = min(iy0 + 1, GRID_H - 1);

    const unsigned row0 = (unsigned)iy0 * GRID_W;
    const unsigned row1 = (unsigned)iy1 * GRID_W;
    const unsigned cq = 8u * (unsigned)lane;
    const uint4 r_nw = *(const uint4*)(tbl + (row0 + ix0) * HALF_C + cq);
    const uint4 r_ne = *(const uint4*)(tbl + (row0 + ix1) * HALF_C + cq);
    const uint4 r_sw = *(const uint4*)(tbl + (row1 + ix0) * HALF_C + cq);
    const uint4 r_se = *(const uint4*)(tbl + (row1 + ix1) * HALF_C + cq);

    float acc[8];
#pragma unroll
    for (int i = 0; i < 8; i++) acc[i] = 0.0f;

    auto accum = [&](const uint4& r, float w) {
        const unsigned u[4] = {r.x, r.y, r.z, r.w};
#pragma unroll
        for (int j = 0; j < 4; j++) {
            const float2 v = __half22float2(*(const __half2*)&u[j]);
            acc[2 * j + 0] = fmaf(v.x, w, acc[2 * j + 0]);
            acc[2 * j + 1] = fmaf(v.y, w, acc[2 * j + 1]);
        }
    };
    accum(r_nw, w_nw);
    accum(r_ne, w_ne);
    accum(r_sw, w_sw);
    accum(r_se, w_se);

    stcs_v8(out + (unsigned)pidx * DIM_FEAT + cq, acc);
}

extern "C" void kernel_launch(void* const* d_in, const int* in_sizes, int n_in,
                              void* d_out, int out_size) {
    const float2* coord = (const float2*)d_in[0];  // [N, 2]
    const float* params = (const float*)d_in[1];   // [1, 32, 1024, 1024]
    float* out = (float*)d_out;                    // [N, 32]
    const int n = in_sizes[0] / 2;

    __half* pt;
    cudaGetSymbolAddress((void**)&pt, g_params_t);

    transpose_kernel<<<HW / 64, 256>>>(params, pt);

    const int threads = 256;
    const long long total = (long long)n * 2;
    const int blocks = (int)((total + threads - 1) / threads);
    // Pass 0: channels 0-15 (table half 0); pass 1: channels 16-31 (half 1).
    sample_kernel<<<blocks, threads>>>(coord, pt, out, n);
    sample_kernel<<<blocks, threads>>>(coord, pt + HALF_ELEMS, out + HALF_C, n);
}

// round 17
// speedup vs baseline: 1.1236x; 1.1236x over previous
#include <cuda_runtime.h>
#include <cuda_fp16.h>
#include <cstdint>

#define GRID_H 1024
#define GRID_W 1024
#define DIM_FEAT 32
#define HW (GRID_H * GRID_W)

// 64 MB table: params transposed to [H, W, C] fp16.
__device__ __half g_params_t[(size_t)DIM_FEAT * HW];

// ---------------------------------------------------------------------------
// Transpose [C, H*W] fp32 -> [H*W, C] fp16.
// Tile: 32 channels x 64 pixels. float4 global reads (coalesced 128B),
// conflict-free smem, 16B v4.b32 table writes (64B per pixel, 4 lanes/pixel).
// Measured at its 192MB traffic floor (~29us).
// ---------------------------------------------------------------------------
__global__ void __launch_bounds__(256)
transpose_kernel(const float* __restrict__ p, __half* __restrict__ pt) {
    __shared__ float tile[32][65];  // 65 pad: conflict-free column reads
    const int pix0 = blockIdx.x * 64;
    const int t = threadIdx.x;      // 0..255

    // Read phase: thread covers float4 xq of channels c and c+16.
    {
        const int c = t >> 4;         // 0..15
        const int xq = t & 15;        // float4 index 0..15 (64 pixels)
        const float4 a = __ldcs((const float4*)(p + (size_t)c * HW + pix0) + xq);
        const float4 b = __ldcs((const float4*)(p + (size_t)(c + 16) * HW + pix0) + xq);
        tile[c][4 * xq + 0] = a.x;
        tile[c][4 * xq + 1] = a.y;
        tile[c][4 * xq + 2] = a.z;
        tile[c][4 * xq + 3] = a.w;
        tile[c + 16][4 * xq + 0] = b.x;
        tile[c + 16][4 * xq + 1] = b.y;
        tile[c + 16][4 * xq + 2] = b.z;
        tile[c + 16][4 * xq + 3] = b.w;
    }
    __syncthreads();

    // Write phase: thread covers 8 channels (cg) of one pixel -> one 16B store.
    {
        const int pix = t >> 2;       // 0..63
        const int cg = t & 3;         // channel group (8 channels)
        const int c0 = 8 * cg;
        uint4 v;
        unsigned* vp = (unsigned*)&v;
#pragma unroll
        for (int j = 0; j < 4; j++) {
            const __half2 h = __floats2half2_rn(tile[c0 + 2 * j][pix],
                                                tile[c0 + 2 * j + 1][pix]);
            vp[j] = *(const unsigned*)&h;
        }
        *(uint4*)(pt + (size_t)(pix0 + pix) * DIM_FEAT + c0) = v;
    }
}

// 256-bit streaming store: one instruction per lane's 8 fp32 channels.
__device__ __forceinline__ void stcs_v8(float* p, const float a[8]) {
    asm volatile(
        "st.global.cs.v8.b32 [%0], {%1,%2,%3,%4,%5,%6,%7,%8};"
        :: "l"(p),
           "f"(a[0]), "f"(a[1]), "f"(a[2]), "f"(a[3]),
           "f"(a[4]), "f"(a[5]), "f"(a[6]), "f"(a[7])
        : "memory");
}

// ---------------------------------------------------------------------------
// Bilinear sample (converged config, 79.9us @ 74.5% HBM): 4 lanes/point,
// lane = 8 channels; 4 x 16B uint4 gathers (64B coalesced per corner);
// one 32B v8 streaming store per lane; 32-bit element offsets.
// ---------------------------------------------------------------------------
__global__ void __launch_bounds__(256, 8)
sample_kernel(const float2* __restrict__ coord,
              const __half* __restrict__ pt,
              float* __restrict__ out, int n) {
    const int t = blockIdx.x * blockDim.x + threadIdx.x;
    const int pidx = t >> 2;     // point index
    const int q = t & 3;         // channel octet (8 channels)
    if (pidx >= n) return;

    const float2 xy = __ldcs(&coord[pidx]);

    // align_corners=True mapping
    const float ix = (xy.x + 1.0f) * 0.5f * (float)(GRID_W - 1);
    const float iy = (xy.y + 1.0f) * 0.5f * (float)(GRID_H - 1);

    const float ix0f = floorf(ix);
    const float iy0f = floorf(iy);
    const float fx = ix - ix0f;
    const float fy = iy - iy0f;

    const float w_nw = (1.0f - fx) * (1.0f - fy);
    const float w_ne = fx * (1.0f - fy);
    const float w_sw = (1.0f - fx) * fy;
    const float w_se = fx * fy;

    int ix0 = min(max((int)ix0f, 0), GRID_W - 1);
    int iy0 = min(max((int)iy0f, 0), GRID_H - 1);
    const int ix1 = min(ix0 + 1, GRID_W - 1);
    const int iy1 = min(iy0 + 1, GRID_H - 1);

    const unsigned row0 = (unsigned)iy0 * GRID_W;
    const unsigned row1 = (unsigned)iy1 * GRID_W;
    const unsigned cq = 8u * (unsigned)q;
    const uint4 r_nw = *(const uint4*)(pt + (row0 + ix0) * DIM_FEAT + cq);
    const uint4 r_ne = *(const uint4*)(pt + (row0 + ix1) * DIM_FEAT + cq);
    const uint4 r_sw = *(const uint4*)(pt + (row1 + ix0) * DIM_FEAT + cq);
    const uint4 r_se = *(const uint4*)(pt + (row1 + ix1) * DIM_FEAT + cq);

    float acc[8];
#pragma unroll
    for (int i = 0; i < 8; i++) acc[i] = 0.0f;

    auto accum = [&](const uint4& r, float w) {
        const unsigned u[4] = {r.x, r.y, r.z, r.w};
#pragma unroll
        for (int j = 0; j < 4; j++) {
            const float2 v = __half22float2(*(const __half2*)&u[j]);
            acc[2 * j + 0] = fmaf(v.x, w, acc[2 * j + 0]);
            acc[2 * j + 1] = fmaf(v.y, w, acc[2 * j + 1]);
        }
    };
    accum(r_nw, w_nw);
    accum(r_ne, w_ne);
    accum(r_sw, w_sw);
    accum(r_se, w_se);

    stcs_v8(out + (unsigned)pidx * DIM_FEAT + cq, acc);
}

extern "C" void kernel_launch(void* const* d_in, const int* in_sizes, int n_in,
                              void* d_out, int out_size) {
    const float2* coord = (const float2*)d_in[0];  // [N, 2]
    const float* params = (const float*)d_in[1];   // [1, 32, 1024, 1024]
    float* out = (float*)d_out;                    // [N, 32]
    const int n = in_sizes[0] / 2;

    __half* pt;
    cudaGetSymbolAddress((void**)&pt, g_params_t);

    transpose_kernel<<<HW / 64, 256>>>(params, pt);

    const int threads = 256;
    const long long total = (long long)n * 4;
    sample_kernel<<<(int)((total + threads - 1) / threads), threads>>>(
        coord, pt, out, n);
}